// round 10
// baseline (speedup 1.0000x reference)
#include <cuda_runtime.h>
#include <cstdint>

#define H96   96
#define HW    9216          // 96*96
#define CIN   256
#define C8C   32
#define NB    16
#define KK    11
#define KTOT  2816          // CIN*KK
#define MTOT  320           // 32 q + 32 k + 256 v output channels fused
#define ATT_N 192

typedef unsigned long long u64;

// ---- packed f32x2 helpers (FFMA2: only reachable via PTX, never from C++) ----
__device__ __forceinline__ u64 pack2(float x) {
    unsigned u = __float_as_uint(x);
    u64 r; asm("mov.b64 %0, {%1, %1};" : "=l"(r) : "r"(u)); return r;
}
__device__ __forceinline__ void fma2(u64& c, u64 a, u64 b) {
    asm("fma.rn.f32x2 %0, %1, %2, %0;" : "+l"(c) : "l"(a), "l"(b));
}
__device__ __forceinline__ float2 unpack2(u64 v) {
    unsigned lo, hi;
    asm("mov.b64 {%0, %1}, %2;" : "=r"(lo), "=r"(hi) : "l"(v));
    return make_float2(__uint_as_float(lo), __uint_as_float(hi));
}

// ---------------- scratch (__device__ globals: allocation-free) ----------------
__device__ float g_wtv[KTOT * MTOT];           // vertical weights, K-major
__device__ float g_wth[KTOT * MTOT];           // horizontal weights, K-major
__device__ float g_qh [NB * C8C * HW];         // NCHW conv outputs
__device__ float g_kh [NB * C8C * HW];
__device__ float g_vh [NB * CIN * HW];
__device__ float g_qw [NB * C8C * HW];
__device__ float g_kw [NB * C8C * HW];
__device__ float g_vw [NB * CIN * HW];
__device__ float g_qhT[NB * C8C * HW];         // [b][c][w][h]
__device__ float g_khT[NB * C8C * HW];
__device__ float g_vhT[NB * CIN * HW];
__device__ float g_att[(size_t)NB * HW * ATT_N];  // [b][h][w][192]
__device__ float g_oh [NB * CIN * HW];         // [b][c][w][h]
__device__ float g_ow [NB * CIN * HW];         // NCHW

// ---------------- weight repack: w[co][ci][dk] -> Wt[k=ci*11+dk][co] ----------
__global__ void prep_weights(const float* __restrict__ wq, const float* __restrict__ wk,
                             const float* __restrict__ wv, float* __restrict__ Wt)
{
    int idx = blockIdx.x * 256 + threadIdx.x;
    if (idx >= KTOT * MTOT) return;
    int k  = idx / MTOT;
    int co = idx - k * MTOT;
    int ci = k / KK;
    int dk = k - ci * KK;
    float v;
    if (co < C8C)            v = wq[(co * CIN + ci) * KK + dk];
    else if (co < 2 * C8C)   v = wk[((co - C8C) * CIN + ci) * KK + dk];
    else                     v = wv[((co - 2 * C8C) * CIN + ci) * KK + dk];
    Wt[idx] = v;
}

// ---------------- fused conv GEMM (implicit im2col) ----------------------------
// DIR=0: vertical (Kx1) shift in h.  DIR=1: horizontal (1xK) shift in w.
// Tile: 64(M) x 128(N) x 16(K), 128 threads, 8x8 microkernel in f32x2 packs.
// Register-prefetch pipeline: tile t+1's LDGs overlap tile t's FFMAs.
template<int DIR>
__global__ void __launch_bounds__(128) conv_gemm(
    const float* __restrict__ x, const float* __restrict__ Wt,
    const float* __restrict__ bq, const float* __restrict__ bk, const float* __restrict__ bv,
    float* __restrict__ oq, float* __restrict__ okk, float* __restrict__ ov)
{
    const int b  = blockIdx.z;
    const int m0 = blockIdx.y * 64;
    const int n0 = blockIdx.x * 128;
    const float* xb = x + (size_t)b * CIN * HW;

    const int tid = threadIdx.x;
    const int tn  = tid & 15;
    const int tm  = tid >> 4;
    const int n   = n0 + tid;            // this thread's B column (spatial idx)
    const int hq  = n / H96;
    const int wq_ = n - hq * H96;

    __shared__ __align__(16) float As[16][64];
    __shared__ __align__(16) float Bs[16][128];

    u64 acc[8][4];                       // 8 m-rows x 4 n-pairs (f32x2)
#pragma unroll
    for (int i = 0; i < 8; i++)
#pragma unroll
        for (int j = 0; j < 4; j++) acc[i][j] = 0ull;

    const int arow = tid >> 6;           // A-load row parity
    const int acol = tid & 63;

    float aReg[8];
    float bReg[16];

    // prologue: fetch tile k0=0 into registers
#pragma unroll
    for (int i = 0; i < 8; i++)
        aReg[i] = Wt[(i * 2 + arow) * MTOT + m0 + acol];
#pragma unroll
    for (int i = 0; i < 16; i++) {
        int ci = i / KK;
        int dk = i - ci * KK;
        float v = 0.f;
        if (DIR == 0) {
            int hp = hq + dk - 5;
            if ((unsigned)hp < (unsigned)H96) v = xb[ci * HW + hp * H96 + wq_];
        } else {
            int wp = wq_ + dk - 5;
            if ((unsigned)wp < (unsigned)H96) v = xb[ci * HW + hq * H96 + wp];
        }
        bReg[i] = v;
    }

    for (int k0 = 0; k0 < KTOT; k0 += 16) {
        // commit prefetched tile to shared
#pragma unroll
        for (int i = 0; i < 8; i++)
            As[i * 2 + arow][acol] = aReg[i];
#pragma unroll
        for (int i = 0; i < 16; i++)
            Bs[i][tid] = bReg[i];
        __syncthreads();

        // prefetch next tile (LDGs fly while we do FFMAs below)
        if (k0 + 16 < KTOT) {
            const int kn = k0 + 16;
#pragma unroll
            for (int i = 0; i < 8; i++)
                aReg[i] = Wt[(kn + i * 2 + arow) * MTOT + m0 + acol];
#pragma unroll
            for (int i = 0; i < 16; i++) {
                int k  = kn + i;
                int ci = k / KK;
                int dk = k - ci * KK;
                float v = 0.f;
                if (DIR == 0) {
                    int hp = hq + dk - 5;
                    if ((unsigned)hp < (unsigned)H96) v = xb[ci * HW + hp * H96 + wq_];
                } else {
                    int wp = wq_ + dk - 5;
                    if ((unsigned)wp < (unsigned)H96) v = xb[ci * HW + hq * H96 + wp];
                }
                bReg[i] = v;
            }
        }

#pragma unroll
        for (int kk = 0; kk < 16; kk++) {
            const float4 a0 = *reinterpret_cast<const float4*>(&As[kk][tm * 8]);
            const float4 a1 = *reinterpret_cast<const float4*>(&As[kk][tm * 8 + 4]);
            u64 ap[8];
            ap[0] = pack2(a0.x); ap[1] = pack2(a0.y); ap[2] = pack2(a0.z); ap[3] = pack2(a0.w);
            ap[4] = pack2(a1.x); ap[5] = pack2(a1.y); ap[6] = pack2(a1.z); ap[7] = pack2(a1.w);
            const u64* b0 = reinterpret_cast<const u64*>(&Bs[kk][tn * 4]);
            const u64* b1 = reinterpret_cast<const u64*>(&Bs[kk][64 + tn * 4]);
            u64 bp[4];
            bp[0] = b0[0]; bp[1] = b0[1]; bp[2] = b1[0]; bp[3] = b1[1];
#pragma unroll
            for (int mi = 0; mi < 8; mi++)
#pragma unroll
                for (int nj = 0; nj < 4; nj++)
                    fma2(acc[mi][nj], ap[mi], bp[nj]);
        }
        __syncthreads();
    }

    // epilogue: bias + scatter to q/k/v buffers (NCHW, coalesced float4)
#pragma unroll
    for (int mi = 0; mi < 8; mi++) {
        int co = m0 + tm * 8 + mi;
        float bias; float* dst;
        if (co < C8C)          { bias = bq[co];            dst = oq  + (size_t)(b * C8C + co) * HW; }
        else if (co < 2 * C8C) { bias = bk[co - C8C];      dst = okk + (size_t)(b * C8C + co - C8C) * HW; }
        else                   { bias = bv[co - 2 * C8C];  dst = ov  + (size_t)(b * CIN + co - 2 * C8C) * HW; }
        float2 p0 = unpack2(acc[mi][0]);
        float2 p1 = unpack2(acc[mi][1]);
        float2 p2 = unpack2(acc[mi][2]);
        float2 p3 = unpack2(acc[mi][3]);
        float4 v0 = make_float4(p0.x + bias, p0.y + bias, p1.x + bias, p1.y + bias);
        float4 v1 = make_float4(p2.x + bias, p2.y + bias, p3.x + bias, p3.y + bias);
        *reinterpret_cast<float4*>(dst + n0 + tn * 4)      = v0;
        *reinterpret_cast<float4*>(dst + n0 + 64 + tn * 4) = v1;
    }
}

// ---------------- (h,w)-plane transpose: [p][h][w] -> [p][w][h] ----------------
__global__ void transpose_hw(const float* __restrict__ in, float* __restrict__ out)
{
    __shared__ float t[32][33];
    const int p  = blockIdx.z;
    const int h0 = blockIdx.y * 32, w0 = blockIdx.x * 32;
    const float* ip = in  + (size_t)p * HW;
    float*       op = out + (size_t)p * HW;
#pragma unroll
    for (int i = threadIdx.y; i < 32; i += 8)
        t[i][threadIdx.x] = ip[(h0 + i) * H96 + w0 + threadIdx.x];
    __syncthreads();
#pragma unroll
    for (int i = threadIdx.y; i < 32; i += 8)
        op[(w0 + i) * H96 + h0 + threadIdx.x] = t[threadIdx.x][i];
}

// ---------------- logits: e[i][j] = sum_c Q[c][i] * K[c][j] --------------------
// MASK=true : vertical path, block = (b, w=s), mask diagonal, att[..][j]
// MASK=false: horizontal path, block = (b, h=s), att[..][96+j]
template<bool MASK>
__global__ void __launch_bounds__(256) logits_kernel(
    const float* __restrict__ Qp, const float* __restrict__ Kp, float* __restrict__ att)
{
    const int bs = blockIdx.x;
    const int b  = bs / H96;
    const int s  = bs - b * H96;
    __shared__ float Qs[C8C][H96];
    __shared__ float Ks[C8C][H96];
    const float* qbase = Qp + (size_t)b * C8C * HW + s * H96;
    const float* kbase = Kp + (size_t)b * C8C * HW + s * H96;
    for (int e = threadIdx.x; e < C8C * H96; e += 256) {
        int c  = e / H96;
        int pp = e - c * H96;
        Qs[c][pp] = qbase[(size_t)c * HW + pp];
        Ks[c][pp] = kbase[(size_t)c * HW + pp];
    }
    __syncthreads();
    const int ti = threadIdx.x & 15, tj = threadIdx.x >> 4;
    const int i0 = ti * 6, j0 = tj * 6;
    float acc[6][6];
#pragma unroll
    for (int i = 0; i < 6; i++)
#pragma unroll
        for (int j = 0; j < 6; j++) acc[i][j] = 0.f;

    for (int c = 0; c < C8C; c++) {
        float a[6], kb[6];
#pragma unroll
        for (int j = 0; j < 6; j++) { a[j] = Qs[c][i0 + j]; kb[j] = Ks[c][j0 + j]; }
#pragma unroll
        for (int i = 0; i < 6; i++)
#pragma unroll
            for (int j = 0; j < 6; j++) acc[i][j] += a[i] * kb[j];
    }
#pragma unroll
    for (int i = 0; i < 6; i++) {
        int qi = i0 + i;
        float* row;
        if (MASK) row = att + ((size_t)((b * H96 + qi) * H96 + s)) * ATT_N + j0;
        else      row = att + ((size_t)((b * H96 + s) * H96 + qi)) * ATT_N + H96 + j0;
#pragma unroll
        for (int j = 0; j < 6; j++) {
            float v = acc[i][j];
            if (MASK && qi == j0 + j) v = -1e30f;   // diagonal -inf mask
            row[j] = v;
        }
    }
}

// ---------------- softmax over 192 contiguous logits, one warp per point -------
__global__ void softmax_kernel(float* __restrict__ att)
{
    const int gw   = (blockIdx.x * blockDim.x + threadIdx.x) >> 5;
    const int lane = threadIdx.x & 31;
    if (gw >= NB * HW) return;
    float* row = att + (size_t)gw * ATT_N;
    float v[6];
    float mx = -1e30f;
#pragma unroll
    for (int i = 0; i < 6; i++) { v[i] = row[lane + 32 * i]; mx = fmaxf(mx, v[i]); }
#pragma unroll
    for (int o = 16; o > 0; o >>= 1) mx = fmaxf(mx, __shfl_xor_sync(0xffffffffu, mx, o));
    float sum = 0.f;
#pragma unroll
    for (int i = 0; i < 6; i++) { v[i] = __expf(v[i] - mx); sum += v[i]; }
#pragma unroll
    for (int o = 16; o > 0; o >>= 1) sum += __shfl_xor_sync(0xffffffffu, sum, o);
    float inv = 1.f / sum;
#pragma unroll
    for (int i = 0; i < 6; i++) row[lane + 32 * i] = v[i] * inv;
}

// ---------------- attention apply: O[c][i] = sum_j V[c][j] * A[i][j] ----------
// MODE=0: out_h, block (b, w=s, c-half), A from att[..][j], O -> [b][c][w][h]
// MODE=1: out_w, block (b, h=s, c-half), A from att[..][96+j], O -> NCHW
// M=128 per block, N=96, K=96 (chunks of 16). f32x2 microkernel.
template<int MODE>
__global__ void __launch_bounds__(256) outgemm_kernel(
    const float* __restrict__ Vp, const float* __restrict__ att, float* __restrict__ O)
{
    const int bs = blockIdx.y;
    const int b  = bs / H96;
    const int s  = bs - b * H96;
    const int c0 = blockIdx.x * 128;
    __shared__ __align__(16) float Vs[16][132];
    __shared__ __align__(16) float Ash[16][100];
    const int tid = threadIdx.x;
    const int tm = tid >> 4, tn = tid & 15;
    u64 acc[8][3];                       // 8 c-rows x 3 i-pairs (f32x2)
#pragma unroll
    for (int i = 0; i < 8; i++)
#pragma unroll
        for (int j = 0; j < 3; j++) acc[i][j] = 0ull;

    const float* vbase = Vp + ((size_t)(b * CIN + c0)) * HW + s * H96;

    for (int k0 = 0; k0 < H96; k0 += 16) {
#pragma unroll
        for (int i = 0; i < 8; i++) {              // 128 c-rows x 16 k
            int e = i * 256 + tid;
            int c = e >> 4, k = e & 15;
            Vs[k][c] = vbase[(size_t)c * HW + k0 + k];
        }
#pragma unroll
        for (int i = 0; i < 6; i++) {              // 96 i-rows x 16 k
            int e = i * 256 + tid;
            int r = e >> 4, k = e & 15;
            size_t aidx;
            if (MODE == 0) aidx = ((size_t)((b * H96 + r) * H96 + s)) * ATT_N + k0 + k;
            else           aidx = ((size_t)((b * H96 + s) * H96 + r)) * ATT_N + H96 + k0 + k;
            Ash[k][r] = att[aidx];
        }
        __syncthreads();
#pragma unroll
        for (int kk = 0; kk < 16; kk++) {
            const float4 a0 = *reinterpret_cast<const float4*>(&Vs[kk][tm * 8]);
            const float4 a1 = *reinterpret_cast<const float4*>(&Vs[kk][tm * 8 + 4]);
            u64 ap[8];
            ap[0] = pack2(a0.x); ap[1] = pack2(a0.y); ap[2] = pack2(a0.z); ap[3] = pack2(a0.w);
            ap[4] = pack2(a1.x); ap[5] = pack2(a1.y); ap[6] = pack2(a1.z); ap[7] = pack2(a1.w);
            // Ash row offset tn*6 floats = 24B -> 8B aligned, base 16B aligned
            const u64* bp64 = reinterpret_cast<const u64*>(&Ash[kk][tn * 6]);
            u64 bp[3] = { bp64[0], bp64[1], bp64[2] };
#pragma unroll
            for (int mi = 0; mi < 8; mi++)
#pragma unroll
                for (int nj = 0; nj < 3; nj++)
                    fma2(acc[mi][nj], ap[mi], bp[nj]);
        }
        __syncthreads();
    }

    float* obase = O + ((size_t)(b * CIN + c0)) * HW + s * H96;
#pragma unroll
    for (int mi = 0; mi < 8; mi++) {
        float* orow = obase + (size_t)(tm * 8 + mi) * HW + tn * 6;
        float2 p0 = unpack2(acc[mi][0]);
        float2 p1 = unpack2(acc[mi][1]);
        float2 p2 = unpack2(acc[mi][2]);
        orow[0] = p0.x; orow[1] = p0.y; orow[2] = p1.x;
        orow[3] = p1.y; orow[4] = p2.x; orow[5] = p2.y;
    }
}

// ---------------- final: out = gamma*(OH^T(h,w) + OW) + x ----------------------
__global__ void final_kernel(const float* __restrict__ OH, const float* __restrict__ OW,
                             const float* __restrict__ x, const float* __restrict__ gamma,
                             float* __restrict__ out)
{
    __shared__ float t[32][33];
    const int p  = blockIdx.z;                 // b*256 + c
    const int h0 = blockIdx.y * 32, w0 = blockIdx.x * 32;
    const size_t base = (size_t)p * HW;
    const float g = gamma[0];
    for (int i = threadIdx.y; i < 32; i += 8)
        t[i][threadIdx.x] = OH[base + (size_t)(w0 + i) * H96 + h0 + threadIdx.x];
    __syncthreads();
    for (int i = threadIdx.y; i < 32; i += 8) {
        size_t idx = base + (size_t)(h0 + i) * H96 + w0 + threadIdx.x;
        out[idx] = g * (t[threadIdx.x][i] + OW[idx]) + x[idx];
    }
}

// ---------------- launch ------------------------------------------------------
extern "C" void kernel_launch(void* const* d_in, const int* in_sizes, int n_in,
                              void* d_out, int out_size)
{
    const float* x     = (const float*)d_in[0];
    const float* wqh   = (const float*)d_in[1];
    const float* bqh   = (const float*)d_in[2];
    const float* wqw   = (const float*)d_in[3];
    const float* bqw   = (const float*)d_in[4];
    const float* wkh   = (const float*)d_in[5];
    const float* bkh   = (const float*)d_in[6];
    const float* wkw   = (const float*)d_in[7];
    const float* bkw   = (const float*)d_in[8];
    const float* wvh   = (const float*)d_in[9];
    const float* bvh   = (const float*)d_in[10];
    const float* wvw   = (const float*)d_in[11];
    const float* bvw   = (const float*)d_in[12];
    const float* gamma = (const float*)d_in[13];
    float* out = (float*)d_out;

    float *wtv, *wth, *qh, *kh, *vh, *qw, *kw, *vw, *qhT, *khT, *vhT, *att, *oh, *ow;
    cudaGetSymbolAddress((void**)&wtv, g_wtv);
    cudaGetSymbolAddress((void**)&wth, g_wth);
    cudaGetSymbolAddress((void**)&qh,  g_qh);
    cudaGetSymbolAddress((void**)&kh,  g_kh);
    cudaGetSymbolAddress((void**)&vh,  g_vh);
    cudaGetSymbolAddress((void**)&qw,  g_qw);
    cudaGetSymbolAddress((void**)&kw,  g_kw);
    cudaGetSymbolAddress((void**)&vw,  g_vw);
    cudaGetSymbolAddress((void**)&qhT, g_qhT);
    cudaGetSymbolAddress((void**)&khT, g_khT);
    cudaGetSymbolAddress((void**)&vhT, g_vhT);
    cudaGetSymbolAddress((void**)&att, g_att);
    cudaGetSymbolAddress((void**)&oh,  g_oh);
    cudaGetSymbolAddress((void**)&ow,  g_ow);

    prep_weights<<<(KTOT * MTOT + 255) / 256, 256>>>(wqh, wkh, wvh, wtv);
    prep_weights<<<(KTOT * MTOT + 255) / 256, 256>>>(wqw, wkw, wvw, wth);

    dim3 cg(72, 5, NB);
    conv_gemm<0><<<cg, 128>>>(x, wtv, bqh, bkh, bvh, qh, kh, vh);
    conv_gemm<1><<<cg, 128>>>(x, wth, bqw, bkw, bvw, qw, kw, vw);

    transpose_hw<<<dim3(3, 3, NB * C8C), dim3(32, 8)>>>(qh, qhT);
    transpose_hw<<<dim3(3, 3, NB * C8C), dim3(32, 8)>>>(kh, khT);
    transpose_hw<<<dim3(3, 3, NB * CIN), dim3(32, 8)>>>(vh, vhT);

    logits_kernel<true ><<<NB * H96, 256>>>(qhT, khT, att);
    logits_kernel<false><<<NB * H96, 256>>>(qw,  kw,  att);

    softmax_kernel<<<(NB * HW) / 8, 256>>>(att);   // 8 warps/block, 1 warp/point

    outgemm_kernel<0><<<dim3(2, NB * H96), 256>>>(vhT, att, oh);
    outgemm_kernel<1><<<dim3(2, NB * H96), 256>>>(vw,  att, ow);

    final_kernel<<<dim3(3, 3, NB * CIN), dim3(32, 8)>>>(oh, ow, x, gamma, out);
}

// round 12
// speedup vs baseline: 1.5713x; 1.5713x over previous
#include <cuda_runtime.h>
#include <cstdint>

#define H96   96
#define HW    9216          // 96*96
#define CIN   256
#define C8C   32
#define NB    16
#define KK    11
#define KTOT  2816          // CIN*KK
#define MQK   64            // 32 q + 32 k fused
#define VM    256           // v output channels
#define ATT_N 192

typedef unsigned long long u64;

// ---- packed f32x2 helpers (FFMA2) ----
__device__ __forceinline__ u64 pack2(float x) {
    unsigned u = __float_as_uint(x);
    u64 r; asm("mov.b64 %0, {%1, %1};" : "=l"(r) : "r"(u)); return r;
}
__device__ __forceinline__ void fma2(u64& c, u64 a, u64 b) {
    asm("fma.rn.f32x2 %0, %1, %2, %0;" : "+l"(c) : "l"(a), "l"(b));
}
__device__ __forceinline__ float2 unpack2(u64 v) {
    unsigned lo, hi;
    asm("mov.b64 {%0, %1}, %2;" : "=r"(lo), "=r"(hi) : "l"(v));
    return make_float2(__uint_as_float(lo), __uint_as_float(hi));
}
__device__ __forceinline__ float to_tf32(float x) {
    unsigned t; asm("cvt.rna.tf32.f32 %0, %1;" : "=r"(t) : "f"(x));
    return __uint_as_float(t);
}

// ---------------- scratch ----------------
__device__ float g_wqkv[KTOT * MQK];          // q/k vertical weights, K-major fp32
__device__ float g_wqkh[KTOT * MQK];          // q/k horizontal
__device__ float g_wvv [KTOT * VM];           // v vertical weights, K-major tf32
__device__ float g_wvh2[KTOT * VM];           // v horizontal
__device__ float g_qh [NB * C8C * HW];
__device__ float g_kh [NB * C8C * HW];
__device__ float g_vh [NB * CIN * HW];
__device__ float g_qw [NB * C8C * HW];
__device__ float g_kw [NB * C8C * HW];
__device__ float g_vw [NB * CIN * HW];
__device__ float g_qhT[NB * C8C * HW];
__device__ float g_khT[NB * C8C * HW];
__device__ float g_vhT[NB * CIN * HW];
__device__ float g_att[(size_t)NB * HW * ATT_N];
__device__ float g_oh [NB * CIN * HW];
__device__ float g_ow [NB * CIN * HW];

// ---------------- weight repack ----------------
__global__ void prep_qk(const float* __restrict__ wq, const float* __restrict__ wk,
                        float* __restrict__ Wt)
{
    int idx = blockIdx.x * 256 + threadIdx.x;
    if (idx >= KTOT * MQK) return;
    int k  = idx / MQK;
    int co = idx - k * MQK;
    int ci = k / KK;
    int dk = k - ci * KK;
    float v = (co < C8C) ? wq[(co * CIN + ci) * KK + dk]
                         : wk[((co - C8C) * CIN + ci) * KK + dk];
    Wt[idx] = v;
}
__global__ void prep_v(const float* __restrict__ wv, float* __restrict__ Wt)
{
    int idx = blockIdx.x * 256 + threadIdx.x;
    if (idx >= KTOT * VM) return;
    int k  = idx / VM;
    int co = idx - k * VM;
    int ci = k / KK;
    int dk = k - ci * KK;
    Wt[idx] = to_tf32(wv[(co * CIN + ci) * KK + dk]);
}

// ---------------- q/k conv GEMM (fp32 FFMA2, M=64) ----------------
template<int DIR>
__global__ void __launch_bounds__(128) qk_conv(
    const float* __restrict__ x, const float* __restrict__ Wt,
    const float* __restrict__ bq, const float* __restrict__ bk,
    float* __restrict__ oq, float* __restrict__ okk)
{
    const int b  = blockIdx.z;
    const int n0 = blockIdx.x * 128;
    const float* xb = x + (size_t)b * CIN * HW;

    const int tid = threadIdx.x;
    const int tn  = tid & 15;
    const int tm  = tid >> 4;
    const int n   = n0 + tid;
    const int hq  = n / H96;
    const int wq_ = n - hq * H96;

    __shared__ __align__(16) float As[16][64];
    __shared__ __align__(16) float Bs[16][128];

    u64 acc[8][4];
#pragma unroll
    for (int i = 0; i < 8; i++)
#pragma unroll
        for (int j = 0; j < 4; j++) acc[i][j] = 0ull;

    const int arow = tid >> 6;
    const int acol = tid & 63;

    float aReg[8];
    float bReg[16];

#pragma unroll
    for (int i = 0; i < 8; i++)
        aReg[i] = Wt[(i * 2 + arow) * MQK + acol];
#pragma unroll
    for (int i = 0; i < 16; i++) {
        int ci = i / KK;
        int dk = i - ci * KK;
        float v = 0.f;
        if (DIR == 0) {
            int hp = hq + dk - 5;
            if ((unsigned)hp < (unsigned)H96) v = xb[ci * HW + hp * H96 + wq_];
        } else {
            int wp = wq_ + dk - 5;
            if ((unsigned)wp < (unsigned)H96) v = xb[ci * HW + hq * H96 + wp];
        }
        bReg[i] = v;
    }

    for (int k0 = 0; k0 < KTOT; k0 += 16) {
#pragma unroll
        for (int i = 0; i < 8; i++)
            As[i * 2 + arow][acol] = aReg[i];
#pragma unroll
        for (int i = 0; i < 16; i++)
            Bs[i][tid] = bReg[i];
        __syncthreads();

        if (k0 + 16 < KTOT) {
            const int kn = k0 + 16;
#pragma unroll
            for (int i = 0; i < 8; i++)
                aReg[i] = Wt[(kn + i * 2 + arow) * MQK + acol];
#pragma unroll
            for (int i = 0; i < 16; i++) {
                int k  = kn + i;
                int ci = k / KK;
                int dk = k - ci * KK;
                float v = 0.f;
                if (DIR == 0) {
                    int hp = hq + dk - 5;
                    if ((unsigned)hp < (unsigned)H96) v = xb[ci * HW + hp * H96 + wq_];
                } else {
                    int wp = wq_ + dk - 5;
                    if ((unsigned)wp < (unsigned)H96) v = xb[ci * HW + hq * H96 + wp];
                }
                bReg[i] = v;
            }
        }

#pragma unroll
        for (int kk = 0; kk < 16; kk++) {
            const float4 a0 = *reinterpret_cast<const float4*>(&As[kk][tm * 8]);
            const float4 a1 = *reinterpret_cast<const float4*>(&As[kk][tm * 8 + 4]);
            u64 ap[8];
            ap[0] = pack2(a0.x); ap[1] = pack2(a0.y); ap[2] = pack2(a0.z); ap[3] = pack2(a0.w);
            ap[4] = pack2(a1.x); ap[5] = pack2(a1.y); ap[6] = pack2(a1.z); ap[7] = pack2(a1.w);
            const u64* b0 = reinterpret_cast<const u64*>(&Bs[kk][tn * 4]);
            const u64* b1 = reinterpret_cast<const u64*>(&Bs[kk][64 + tn * 4]);
            u64 bp[4];
            bp[0] = b0[0]; bp[1] = b0[1]; bp[2] = b1[0]; bp[3] = b1[1];
#pragma unroll
            for (int mi = 0; mi < 8; mi++)
#pragma unroll
                for (int nj = 0; nj < 4; nj++)
                    fma2(acc[mi][nj], ap[mi], bp[nj]);
        }
        __syncthreads();
    }

#pragma unroll
    for (int mi = 0; mi < 8; mi++) {
        int co = tm * 8 + mi;
        float bias; float* dst;
        if (co < C8C) { bias = bq[co];       dst = oq  + (size_t)(b * C8C + co) * HW; }
        else          { bias = bk[co - C8C]; dst = okk + (size_t)(b * C8C + co - C8C) * HW; }
        float2 p0 = unpack2(acc[mi][0]);
        float2 p1 = unpack2(acc[mi][1]);
        float2 p2 = unpack2(acc[mi][2]);
        float2 p3 = unpack2(acc[mi][3]);
        float4 v0 = make_float4(p0.x + bias, p0.y + bias, p1.x + bias, p1.y + bias);
        float4 v1 = make_float4(p2.x + bias, p2.y + bias, p3.x + bias, p3.y + bias);
        *reinterpret_cast<float4*>(dst + n0 + tn * 4)      = v0;
        *reinterpret_cast<float4*>(dst + n0 + 64 + tn * 4) = v1;
    }
}

// ---------------- v conv GEMM (tf32 mma.sync, M=256) ----------------
// Block 256 thr = 8 warps, tile M=128(c) x N=128(spatial) x K=32.
// Warp grid 2(M)x4(N): warptile 64x32 = 4 m-tiles x 4 n-tiles of m16n8k8.
template<int DIR>
__global__ void __launch_bounds__(256) v_conv(
    const float* __restrict__ x, const float* __restrict__ Wt,
    const float* __restrict__ bv, float* __restrict__ ov)
{
    const int b  = blockIdx.z;
    const int c0 = blockIdx.y * 128;
    const int n0 = blockIdx.x * 128;
    const float* xb = x + (size_t)b * CIN * HW;

    const int tid  = threadIdx.x;
    const int warp = tid >> 5, lane = tid & 31;
    const int wm = warp & 1, wn = warp >> 1;
    const int g  = lane >> 2, tg = lane & 3;

    __shared__ __align__(16) float As[32][136];   // [k][c], pad 8 -> conflict-free frags
    __shared__ __align__(16) float Bs[32][136];   // [k][n]

    const int ncol  = tid & 127;
    const int rbase = tid >> 7;          // 0/1
    const int n   = n0 + ncol;
    const int hq  = n / H96;
    const int wq_ = n - hq * H96;

    float acc[4][4][4];
#pragma unroll
    for (int a = 0; a < 4; a++)
#pragma unroll
        for (int q = 0; q < 4; q++)
#pragma unroll
            for (int r = 0; r < 4; r++) acc[a][q][r] = 0.f;

    float aReg[16], bReg[16];

    // prologue: tile k0 = 0
#pragma unroll
    for (int it = 0; it < 16; it++)
        aReg[it] = Wt[(size_t)(2 * it + rbase) * VM + c0 + ncol];
#pragma unroll
    for (int it = 0; it < 16; it++) {
        int k  = 2 * it + rbase;
        int ci = k / KK, dk = k - ci * KK;
        float v = 0.f;
        if (DIR == 0) {
            int hp = hq + dk - 5;
            if ((unsigned)hp < (unsigned)H96) v = xb[ci * HW + hp * H96 + wq_];
        } else {
            int wp = wq_ + dk - 5;
            if ((unsigned)wp < (unsigned)H96) v = xb[ci * HW + hq * H96 + wp];
        }
        bReg[it] = v;
    }

    for (int k0 = 0; k0 < KTOT; k0 += 32) {
#pragma unroll
        for (int it = 0; it < 16; it++) {
            int r = 2 * it + rbase;
            As[r][ncol] = aReg[it];
            Bs[r][ncol] = to_tf32(bReg[it]);
        }
        __syncthreads();

        if (k0 + 32 < KTOT) {
            const int kn = k0 + 32;
#pragma unroll
            for (int it = 0; it < 16; it++)
                aReg[it] = Wt[(size_t)(kn + 2 * it + rbase) * VM + c0 + ncol];
#pragma unroll
            for (int it = 0; it < 16; it++) {
                int k  = kn + 2 * it + rbase;
                int ci = k / KK, dk = k - ci * KK;
                float v = 0.f;
                if (DIR == 0) {
                    int hp = hq + dk - 5;
                    if ((unsigned)hp < (unsigned)H96) v = xb[ci * HW + hp * H96 + wq_];
                } else {
                    int wp = wq_ + dk - 5;
                    if ((unsigned)wp < (unsigned)H96) v = xb[ci * HW + hq * H96 + wp];
                }
                bReg[it] = v;
            }
        }

#pragma unroll
        for (int k8 = 0; k8 < 4; k8++) {
            const int kr = k8 * 8;
            unsigned af[4][4], bf[4][2];
#pragma unroll
            for (int mt = 0; mt < 4; mt++) {
                int mrow = wm * 64 + mt * 16 + g;
                af[mt][0] = __float_as_uint(As[kr + tg][mrow]);
                af[mt][1] = __float_as_uint(As[kr + tg][mrow + 8]);
                af[mt][2] = __float_as_uint(As[kr + tg + 4][mrow]);
                af[mt][3] = __float_as_uint(As[kr + tg + 4][mrow + 8]);
            }
#pragma unroll
            for (int nt = 0; nt < 4; nt++) {
                int nc = wn * 32 + nt * 8 + g;
                bf[nt][0] = __float_as_uint(Bs[kr + tg][nc]);
                bf[nt][1] = __float_as_uint(Bs[kr + tg + 4][nc]);
            }
#pragma unroll
            for (int mt = 0; mt < 4; mt++)
#pragma unroll
                for (int nt = 0; nt < 4; nt++)
                    asm volatile(
                        "mma.sync.aligned.m16n8k8.row.col.f32.tf32.tf32.f32 "
                        "{%0,%1,%2,%3}, {%4,%5,%6,%7}, {%8,%9}, {%0,%1,%2,%3};"
                        : "+f"(acc[mt][nt][0]), "+f"(acc[mt][nt][1]),
                          "+f"(acc[mt][nt][2]), "+f"(acc[mt][nt][3])
                        : "r"(af[mt][0]), "r"(af[mt][1]), "r"(af[mt][2]), "r"(af[mt][3]),
                          "r"(bf[nt][0]), "r"(bf[nt][1]));
        }
        __syncthreads();
    }

    // epilogue: bias + store NCHW
#pragma unroll
    for (int mt = 0; mt < 4; mt++) {
        int crow0 = c0 + wm * 64 + mt * 16 + g;
        float bias0 = bv[crow0];
        float bias1 = bv[crow0 + 8];
        float* d0 = ov + (size_t)(b * CIN + crow0) * HW;
        float* d1 = ov + (size_t)(b * CIN + crow0 + 8) * HW;
#pragma unroll
        for (int nt = 0; nt < 4; nt++) {
            int nn = n0 + wn * 32 + nt * 8 + 2 * tg;
            d0[nn]     = acc[mt][nt][0] + bias0;
            d0[nn + 1] = acc[mt][nt][1] + bias0;
            d1[nn]     = acc[mt][nt][2] + bias1;
            d1[nn + 1] = acc[mt][nt][3] + bias1;
        }
    }
}

// ---------------- (h,w)-plane transpose ----------------
__global__ void transpose_hw(const float* __restrict__ in, float* __restrict__ out)
{
    __shared__ float t[32][33];
    const int p  = blockIdx.z;
    const int h0 = blockIdx.y * 32, w0 = blockIdx.x * 32;
    const float* ip = in  + (size_t)p * HW;
    float*       op = out + (size_t)p * HW;
#pragma unroll
    for (int i = threadIdx.y; i < 32; i += 8)
        t[i][threadIdx.x] = ip[(h0 + i) * H96 + w0 + threadIdx.x];
    __syncthreads();
#pragma unroll
    for (int i = threadIdx.y; i < 32; i += 8)
        op[(w0 + i) * H96 + h0 + threadIdx.x] = t[threadIdx.x][i];
}

// ---------------- logits ----------------
template<bool MASK>
__global__ void __launch_bounds__(256) logits_kernel(
    const float* __restrict__ Qp, const float* __restrict__ Kp, float* __restrict__ att)
{
    const int bs = blockIdx.x;
    const int b  = bs / H96;
    const int s  = bs - b * H96;
    __shared__ float Qs[C8C][H96];
    __shared__ float Ks[C8C][H96];
    const float* qbase = Qp + (size_t)b * C8C * HW + s * H96;
    const float* kbase = Kp + (size_t)b * C8C * HW + s * H96;
    for (int e = threadIdx.x; e < C8C * H96; e += 256) {
        int c  = e / H96;
        int pp = e - c * H96;
        Qs[c][pp] = qbase[(size_t)c * HW + pp];
        Ks[c][pp] = kbase[(size_t)c * HW + pp];
    }
    __syncthreads();
    const int ti = threadIdx.x & 15, tj = threadIdx.x >> 4;
    const int i0 = ti * 6, j0 = tj * 6;
    float acc[6][6];
#pragma unroll
    for (int i = 0; i < 6; i++)
#pragma unroll
        for (int j = 0; j < 6; j++) acc[i][j] = 0.f;

    for (int c = 0; c < C8C; c++) {
        float a[6], kb[6];
#pragma unroll
        for (int j = 0; j < 6; j++) { a[j] = Qs[c][i0 + j]; kb[j] = Ks[c][j0 + j]; }
#pragma unroll
        for (int i = 0; i < 6; i++)
#pragma unroll
            for (int j = 0; j < 6; j++) acc[i][j] += a[i] * kb[j];
    }
#pragma unroll
    for (int i = 0; i < 6; i++) {
        int qi = i0 + i;
        float* row;
        if (MASK) row = att + ((size_t)((b * H96 + qi) * H96 + s)) * ATT_N + j0;
        else      row = att + ((size_t)((b * H96 + s) * H96 + qi)) * ATT_N + H96 + j0;
#pragma unroll
        for (int j = 0; j < 6; j++) {
            float v = acc[i][j];
            if (MASK && qi == j0 + j) v = -1e30f;
            row[j] = v;
        }
    }
}

// ---------------- softmax ----------------
__global__ void softmax_kernel(float* __restrict__ att)
{
    const int gw   = (blockIdx.x * blockDim.x + threadIdx.x) >> 5;
    const int lane = threadIdx.x & 31;
    if (gw >= NB * HW) return;
    float* row = att + (size_t)gw * ATT_N;
    float v[6];
    float mx = -1e30f;
#pragma unroll
    for (int i = 0; i < 6; i++) { v[i] = row[lane + 32 * i]; mx = fmaxf(mx, v[i]); }
#pragma unroll
    for (int o = 16; o > 0; o >>= 1) mx = fmaxf(mx, __shfl_xor_sync(0xffffffffu, mx, o));
    float sum = 0.f;
#pragma unroll
    for (int i = 0; i < 6; i++) { v[i] = __expf(v[i] - mx); sum += v[i]; }
#pragma unroll
    for (int o = 16; o > 0; o >>= 1) sum += __shfl_xor_sync(0xffffffffu, sum, o);
    float inv = 1.f / sum;
#pragma unroll
    for (int i = 0; i < 6; i++) row[lane + 32 * i] = v[i] * inv;
}

// ---------------- attention apply ----------------
template<int MODE>
__global__ void __launch_bounds__(256) outgemm_kernel(
    const float* __restrict__ Vp, const float* __restrict__ att, float* __restrict__ O)
{
    const int bs = blockIdx.y;
    const int b  = bs / H96;
    const int s  = bs - b * H96;
    const int c0 = blockIdx.x * 128;
    __shared__ __align__(16) float Vs[16][132];
    __shared__ __align__(16) float Ash[16][100];
    const int tid = threadIdx.x;
    const int tm = tid >> 4, tn = tid & 15;
    u64 acc[8][3];
#pragma unroll
    for (int i = 0; i < 8; i++)
#pragma unroll
        for (int j = 0; j < 3; j++) acc[i][j] = 0ull;

    const float* vbase = Vp + ((size_t)(b * CIN + c0)) * HW + s * H96;

    for (int k0 = 0; k0 < H96; k0 += 16) {
#pragma unroll
        for (int i = 0; i < 8; i++) {
            int e = i * 256 + tid;
            int c = e >> 4, k = e & 15;
            Vs[k][c] = vbase[(size_t)c * HW + k0 + k];
        }
#pragma unroll
        for (int i = 0; i < 6; i++) {
            int e = i * 256 + tid;
            int r = e >> 4, k = e & 15;
            size_t aidx;
            if (MODE == 0) aidx = ((size_t)((b * H96 + r) * H96 + s)) * ATT_N + k0 + k;
            else           aidx = ((size_t)((b * H96 + s) * H96 + r)) * ATT_N + H96 + k0 + k;
            Ash[k][r] = att[aidx];
        }
        __syncthreads();
#pragma unroll
        for (int kk = 0; kk < 16; kk++) {
            const float4 a0 = *reinterpret_cast<const float4*>(&Vs[kk][tm * 8]);
            const float4 a1 = *reinterpret_cast<const float4*>(&Vs[kk][tm * 8 + 4]);
            u64 ap[8];
            ap[0] = pack2(a0.x); ap[1] = pack2(a0.y); ap[2] = pack2(a0.z); ap[3] = pack2(a0.w);
            ap[4] = pack2(a1.x); ap[5] = pack2(a1.y); ap[6] = pack2(a1.z); ap[7] = pack2(a1.w);
            const u64* bp64 = reinterpret_cast<const u64*>(&Ash[kk][tn * 6]);
            u64 bp[3] = { bp64[0], bp64[1], bp64[2] };
#pragma unroll
            for (int mi = 0; mi < 8; mi++)
#pragma unroll
                for (int nj = 0; nj < 3; nj++)
                    fma2(acc[mi][nj], ap[mi], bp[nj]);
        }
        __syncthreads();
    }

    float* obase = O + ((size_t)(b * CIN + c0)) * HW + s * H96;
#pragma unroll
    for (int mi = 0; mi < 8; mi++) {
        float* orow = obase + (size_t)(tm * 8 + mi) * HW + tn * 6;
        float2 p0 = unpack2(acc[mi][0]);
        float2 p1 = unpack2(acc[mi][1]);
        float2 p2 = unpack2(acc[mi][2]);
        orow[0] = p0.x; orow[1] = p0.y; orow[2] = p1.x;
        orow[3] = p1.y; orow[4] = p2.x; orow[5] = p2.y;
    }
}

// ---------------- final ----------------
__global__ void final_kernel(const float* __restrict__ OH, const float* __restrict__ OW,
                             const float* __restrict__ x, const float* __restrict__ gamma,
                             float* __restrict__ out)
{
    __shared__ float t[32][33];
    const int p  = blockIdx.z;
    const int h0 = blockIdx.y * 32, w0 = blockIdx.x * 32;
    const size_t base = (size_t)p * HW;
    const float g = gamma[0];
    for (int i = threadIdx.y; i < 32; i += 8)
        t[i][threadIdx.x] = OH[base + (size_t)(w0 + i) * H96 + h0 + threadIdx.x];
    __syncthreads();
    for (int i = threadIdx.y; i < 32; i += 8) {
        size_t idx = base + (size_t)(h0 + i) * H96 + w0 + threadIdx.x;
        out[idx] = g * (t[threadIdx.x][i] + OW[idx]) + x[idx];
    }
}

// ---------------- launch ----------------
extern "C" void kernel_launch(void* const* d_in, const int* in_sizes, int n_in,
                              void* d_out, int out_size)
{
    const float* x     = (const float*)d_in[0];
    const float* wqh   = (const float*)d_in[1];
    const float* bqh   = (const float*)d_in[2];
    const float* wqw   = (const float*)d_in[3];
    const float* bqw   = (const float*)d_in[4];
    const float* wkh   = (const float*)d_in[5];
    const float* bkh   = (const float*)d_in[6];
    const float* wkw   = (const float*)d_in[7];
    const float* bkw   = (const float*)d_in[8];
    const float* wvh   = (const float*)d_in[9];
    const float* bvh   = (const float*)d_in[10];
    const float* wvw   = (const float*)d_in[11];
    const float* bvw   = (const float*)d_in[12];
    const float* gamma = (const float*)d_in[13];
    float* out = (float*)d_out;

    float *wqkv, *wqkh, *wvv, *wvh2, *qh, *kh, *vh, *qw, *kw, *vw,
          *qhT, *khT, *vhT, *att, *oh, *ow;
    cudaGetSymbolAddress((void**)&wqkv, g_wqkv);
    cudaGetSymbolAddress((void**)&wqkh, g_wqkh);
    cudaGetSymbolAddress((void**)&wvv,  g_wvv);
    cudaGetSymbolAddress((void**)&wvh2, g_wvh2);
    cudaGetSymbolAddress((void**)&qh,  g_qh);
    cudaGetSymbolAddress((void**)&kh,  g_kh);
    cudaGetSymbolAddress((void**)&vh,  g_vh);
    cudaGetSymbolAddress((void**)&qw,  g_qw);
    cudaGetSymbolAddress((void**)&kw,  g_kw);
    cudaGetSymbolAddress((void**)&vw,  g_vw);
    cudaGetSymbolAddress((void**)&qhT, g_qhT);
    cudaGetSymbolAddress((void**)&khT, g_khT);
    cudaGetSymbolAddress((void**)&vhT, g_vhT);
    cudaGetSymbolAddress((void**)&att, g_att);
    cudaGetSymbolAddress((void**)&oh,  g_oh);
    cudaGetSymbolAddress((void**)&ow,  g_ow);

    prep_qk<<<(KTOT * MQK + 255) / 256, 256>>>(wqh, wkh, wqkv);
    prep_qk<<<(KTOT * MQK + 255) / 256, 256>>>(wqw, wkw, wqkh);
    prep_v <<<(KTOT * VM  + 255) / 256, 256>>>(wvh, wvv);
    prep_v <<<(KTOT * VM  + 255) / 256, 256>>>(wvw, wvh2);

    qk_conv<0><<<dim3(72, 1, NB), 128>>>(x, wqkv, bqh, bkh, qh, kh);
    qk_conv<1><<<dim3(72, 1, NB), 128>>>(x, wqkh, bqw, bkw, qw, kw);
    v_conv<0><<<dim3(72, 2, NB), 256>>>(x, wvv,  bvh, vh);
    v_conv<1><<<dim3(72, 2, NB), 256>>>(x, wvh2, bvw, vw);

    transpose_hw<<<dim3(3, 3, NB * C8C), dim3(32, 8)>>>(qh, qhT);
    transpose_hw<<<dim3(3, 3, NB * C8C), dim3(32, 8)>>>(kh, khT);
    transpose_hw<<<dim3(3, 3, NB * CIN), dim3(32, 8)>>>(vh, vhT);

    logits_kernel<true ><<<NB * H96, 256>>>(qhT, khT, att);
    logits_kernel<false><<<NB * H96, 256>>>(qw,  kw,  att);

    softmax_kernel<<<(NB * HW) / 8, 256>>>(att);

    outgemm_kernel<0><<<dim3(2, NB * H96), 256>>>(vhT, att, oh);
    outgemm_kernel<1><<<dim3(2, NB * H96), 256>>>(vw,  att, ow);

    final_kernel<<<dim3(3, 3, NB * CIN), dim3(32, 8)>>>(oh, ow, x, gamma, out);
}